// round 10
// baseline (speedup 1.0000x reference)
#include <cuda_runtime.h>
#include <cuda_fp16.h>
#include <cstdint>

// Q4 group-quantized linear: out = x @ W^T + bias (harness promotes fp16 -> fp32)
// compute_103 toolchain => no tcgen05; HMMA mma.sync path.
// R10 == R9 resubmit (infra failure last round):
//     register-B (no B smem) + renibbled packing (2-op extraction) +
//     B prefetch one kt ahead + 3-stage A-only cp.async pipeline.
//     CTA 128x128, BK=64, 256 thr (8 warps 2x4, warp 64x32), 2 CTAs/SM.

#define M_TOTAL 8192
#define K_TOTAL 4096
#define N_TOTAL 11008
#define BM 128
#define BN 128
#define BK 64
#define NKT (K_TOTAL / BK)     // 64
#define LDS 72                 // halves per A smem row (conflict-free ldmatrix)
#define A_STAGE_H (BM * LDS)   // 9216 halves
#define N_GROUPS 352256

// ---- scratch (device globals; no runtime allocation) ----
__device__ __align__(16) __half             g_x16[(size_t)M_TOTAL * K_TOTAL];   // 64 MB
__device__ __align__(16) unsigned long long g_qt[(size_t)N_TOTAL * 256];        // 22.5 MB
__device__ __align__(4)  __half2            g_sz[N_GROUPS];                     // (s,z)

// ---- preprocess: fp32 x -> fp16 ----
__global__ void convert_x_kernel(const float* __restrict__ x) {
    size_t base = ((size_t)blockIdx.x * blockDim.x + threadIdx.x) * 8;
    float4 a = *(const float4*)&x[base];
    float4 b = *(const float4*)&x[base + 4];
    __half2 h[4] = { __floats2half2_rn(a.x, a.y), __floats2half2_rn(a.z, a.w),
                     __floats2half2_rn(b.x, b.y), __floats2half2_rn(b.z, b.w) };
    *(uint4*)&g_x16[base] = *(uint4*)h;
}

// ---- preprocess: qweight -> renibbled fragment-native u64 layout ----
// Thread t = (n, kt64). Reads the 32-byte k-slab (k = 0..63 of this tile).
// For GEMM thread j (=lane&3), u64_j = two u32 words (w2=0: k-steps 0,1;
// w2=1: k-steps 2,3). Within a u32, nibble i holds element el[i] with:
//   el = {A+2j, A+8+2j, B+2j, B+8+2j, A+2j+1, A+8+2j+1, B+2j+1, B+8+2j+1}
// (A = 32*w2, B = A+16), so (v>>s) & 0x000F000F (s=0,4,8,12) yields the four
// mma B-fragment half2s {ksA.b0, ksA.b1, ksB.b0, ksB.b1} directly.
__global__ void repack_qt_kernel(const int* __restrict__ qw) {
    int t = blockIdx.x * blockDim.x + threadIdx.x;     // 0 .. N_TOTAL*64-1
    size_t base = (size_t)t * 32;
    int w[32];
    const int4* p = (const int4*)(qw + base);
    #pragma unroll
    for (int q = 0; q < 8; ++q) {
        int4 v = p[q];
        w[4 * q] = v.x; w[4 * q + 1] = v.y; w[4 * q + 2] = v.z; w[4 * q + 3] = v.w;
    }
    unsigned nib[64];
    #pragma unroll
    for (int i = 0; i < 32; ++i) {
        nib[2 * i]     = (unsigned)w[i] & 0xFu;
        nib[2 * i + 1] = ((unsigned)w[i] >> 4) & 0xFu;
    }
    #pragma unroll
    for (int j = 0; j < 4; ++j) {
        unsigned long long v = 0;
        #pragma unroll
        for (int w2 = 0; w2 < 2; ++w2) {
            int A = 32 * w2;
            int B = A + 16;
            int el[8] = { A + 2 * j,     A + 8 + 2 * j,     B + 2 * j,     B + 8 + 2 * j,
                          A + 2 * j + 1, A + 8 + 2 * j + 1, B + 2 * j + 1, B + 8 + 2 * j + 1 };
            #pragma unroll
            for (int i = 0; i < 8; ++i)
                v |= (unsigned long long)nib[el[i]] << (4 * (8 * w2 + i));
        }
        g_qt[(size_t)t * 4 + j] = v;
    }
}

__global__ void pack_sz_kernel(const float* __restrict__ s, const float* __restrict__ z) {
    int i = blockIdx.x * blockDim.x + threadIdx.x;
    g_sz[i] = __floats2half2_rn(s[i], z[i]);
}

// renibbled dequant: u32 -> 4 half2 {ksA.b0, ksA.b1, ksB.b0, ksB.b1}
__device__ __forceinline__ void dqx(uint32_t v, __half2 s2, __half2 z2, __half2 k1032,
                                    __half2* o) {
    uint32_t t0 = (v & 0x000F000Fu) | 0x64006400u;
    uint32_t t1 = ((v >> 4) & 0x000F000Fu) | 0x64006400u;
    uint32_t t2 = ((v >> 8) & 0x000F000Fu) | 0x64006400u;
    uint32_t t3 = ((v >> 12) & 0x000F000Fu) | 0x64006400u;
    o[0] = __hfma2(__hsub2(*(__half2*)&t0, k1032), s2, z2);
    o[1] = __hfma2(__hsub2(*(__half2*)&t1, k1032), s2, z2);
    o[2] = __hfma2(__hsub2(*(__half2*)&t2, k1032), s2, z2);
    o[3] = __hfma2(__hsub2(*(__half2*)&t3, k1032), s2, z2);
}

__global__ __launch_bounds__(256, 2)
void q4gemm_kernel(const float* __restrict__ bias,
                   float*       __restrict__ out)
{
    __shared__ __half sA[3][A_STAGE_H];    // 55.3 KB static; B lives in registers

    const int tid  = threadIdx.x;
    const int wid  = tid >> 5;             // 0..7
    const int lane = tid & 31;
    const int warp_m = wid & 1;            // 0..1 (64 rows)
    const int warp_n = wid >> 1;           // 0..3 (32 cols)
    const int m0 = blockIdx.y * BM;
    const int n0 = blockIdx.x * BN;

    float acc[4][4][4];
    #pragma unroll
    for (int mi = 0; mi < 4; ++mi)
        #pragma unroll
        for (int ni = 0; ni < 4; ++ni)
            #pragma unroll
            for (int r = 0; r < 4; ++r)
                acc[mi][ni][r] = 0.0f;

    const int j4 = lane & 3;
    const __half2 k1032 = __floats2half2_rn(1032.0f, 1032.0f);
    const unsigned long long* qtp[4];
    int szb[4];
    #pragma unroll
    for (int ni = 0; ni < 4; ++ni) {
        int n = n0 + warp_n * 32 + ni * 8 + (lane >> 2);
        qtp[ni] = g_qt + (size_t)n * 256 + j4;
        szb[ni] = n * 32;
    }

    auto issue_a = [&](int kt, int st) {
        const __half* src_base = g_x16 + (size_t)m0 * K_TOTAL + kt * BK;
        #pragma unroll
        for (int i = 0; i < 4; ++i) {
            int u = tid + i * 256;          // 16B chunk 0..1023
            int r = u >> 3;
            int c = (u & 7) << 3;
            uint32_t daddr = (uint32_t)__cvta_generic_to_shared(&sA[st][r * LDS + c]);
            const __half* gsrc = src_base + (size_t)r * K_TOTAL + c;
            asm volatile("cp.async.cg.shared.global [%0], [%1], 16;"
                         :: "r"(daddr), "l"(gsrc));
        }
        asm volatile("cp.async.commit_group;");
    };

    // ---- prologue: issue A stages 0,1; preload B for kt=0 ----
    issue_a(0, 0);
    issue_a(1, 1);
    unsigned long long bu[4];
    #pragma unroll
    for (int ni = 0; ni < 4; ++ni) bu[ni] = qtp[ni][0];
    asm volatile("cp.async.wait_group 1;");
    __syncthreads();

    for (int kt = 0; kt < NKT; ++kt) {
        const int cur = kt % 3;
        if (kt + 2 < NKT) issue_a(kt + 2, (kt + 2) % 3);

        // prefetch next kt's B words (overlaps with compute below)
        unsigned long long bu2[4];
        if (kt + 1 < NKT) {
            #pragma unroll
            for (int ni = 0; ni < 4; ++ni) bu2[ni] = qtp[ni][(kt + 1) * 4];
        }

        // per-group scale/zero (group spans 2 kts; L1-resident)
        __half2 s2[4], z2[4];
        #pragma unroll
        for (int ni = 0; ni < 4; ++ni) {
            __half2 sz = g_sz[szb[ni] + (kt >> 1)];
            s2[ni] = __half2half2(__low2half(sz));
            z2[ni] = __half2half2(__high2half(sz));
        }

        const __half* cA = sA[cur];
        #pragma unroll
        for (int kp = 0; kp < 2; ++kp) {
            __half2 bf[4][4];
            #pragma unroll
            for (int ni = 0; ni < 4; ++ni)
                dqx((uint32_t)(bu[ni] >> (32 * kp)), s2[ni], z2[ni], k1032, bf[ni]);

            #pragma unroll
            for (int ks2 = 0; ks2 < 2; ++ks2) {
                const int ks = kp * 2 + ks2;
                uint32_t af[4][4];
                #pragma unroll
                for (int mi = 0; mi < 4; ++mi) {
                    int row = warp_m * 64 + mi * 16 + (lane & 15);
                    int col = ks * 16 + ((lane >> 4) << 3);
                    uint32_t addr = (uint32_t)__cvta_generic_to_shared(cA + row * LDS + col);
                    asm volatile(
                        "ldmatrix.sync.aligned.m8n8.x4.shared.b16 {%0,%1,%2,%3}, [%4];"
                        : "=r"(af[mi][0]), "=r"(af[mi][1]),
                          "=r"(af[mi][2]), "=r"(af[mi][3])
                        : "r"(addr));
                }
                #pragma unroll
                for (int mi = 0; mi < 4; ++mi)
                    #pragma unroll
                    for (int ni = 0; ni < 4; ++ni)
                        asm volatile(
                            "mma.sync.aligned.m16n8k16.row.col.f32.f16.f16.f32 "
                            "{%0,%1,%2,%3}, {%4,%5,%6,%7}, {%8,%9}, {%0,%1,%2,%3};"
                            : "+f"(acc[mi][ni][0]), "+f"(acc[mi][ni][1]),
                              "+f"(acc[mi][ni][2]), "+f"(acc[mi][ni][3])
                            : "r"(af[mi][0]), "r"(af[mi][1]),
                              "r"(af[mi][2]), "r"(af[mi][3]),
                              "r"(*(const uint32_t*)&bf[ni][2 * ks2]),
                              "r"(*(const uint32_t*)&bf[ni][2 * ks2 + 1]));
            }
        }

        if (kt + 1 < NKT) {
            #pragma unroll
            for (int ni = 0; ni < 4; ++ni) bu[ni] = bu2[ni];
        }

        // ensure stage (kt+1)%3 is resident before next iteration reads it
        if (kt + 2 < NKT) { asm volatile("cp.async.wait_group 1;"); }
        else              { asm volatile("cp.async.wait_group 0;"); }
        __syncthreads();
    }

    // ---- epilogue: bias + fp16 rounding (match reference), fp32 store ----
    #pragma unroll
    for (int mi = 0; mi < 4; ++mi) {
        #pragma unroll
        for (int ni = 0; ni < 4; ++ni) {
            int m = m0 + warp_m * 64 + mi * 16 + (lane >> 2);
            int n = n0 + warp_n * 32 + ni * 8 + (lane & 3) * 2;
            float b0 = bias[n];
            float b1 = bias[n + 1];
            float2 r0 = make_float2(__half2float(__float2half(acc[mi][ni][0] + b0)),
                                    __half2float(__float2half(acc[mi][ni][1] + b1)));
            float2 r1 = make_float2(__half2float(__float2half(acc[mi][ni][2] + b0)),
                                    __half2float(__float2half(acc[mi][ni][3] + b1)));
            *(float2*)&out[(size_t)m * N_TOTAL + n]       = r0;
            *(float2*)&out[(size_t)(m + 8) * N_TOTAL + n] = r1;
        }
    }
}

extern "C" void kernel_launch(void* const* d_in, const int* in_sizes, int n_in,
                              void* d_out, int out_size)
{
    const float* x      = (const float*)d_in[0];
    const int*   qw     = (const int*)  d_in[1];
    const float* scales = (const float*)d_in[2];
    const float* zeros  = (const float*)d_in[3];
    const float* bias   = (const float*)d_in[4];
    float*       out    = (float*)d_out;

    convert_x_kernel<<<(M_TOTAL * (size_t)K_TOTAL) / 8 / 256, 256>>>(x);
    repack_qt_kernel<<<(N_TOTAL * 64) / 256, 256>>>(qw);   // 2752 blocks
    pack_sz_kernel<<<N_GROUPS / 256, 256>>>(scales, zeros);

    dim3 grid(N_TOTAL / BN, M_TOTAL / BM);   // 86 x 64
    q4gemm_kernel<<<grid, 256>>>(bias, out);
}